// round 15
// baseline (speedup 1.0000x reference)
#include <cuda_runtime.h>
#include <math.h>

// Problem constants
#define BATCH   4
#define NNODES  325
#define BN      (BATCH * NNODES)   // 1300
#define IDIM    64
#define HDIM    128
#define G4H     (4 * HDIM)         // 512
#define MAXNB   96
#define LN_EPS  1e-5f

// ---------------- scratch (__device__ globals; no allocation) ----------------
__device__ float g_gates[BN * G4H];
__device__ float g_h_lstm[BN * HDIM];
__device__ float g_support[BN * HDIM];
__device__ float g_hgraph[BN * HDIM];
__device__ float g_P[BN * HDIM];          // support @ Ws^T
__device__ float g_Q[BN * HDIM];          // support @ Wt^T
__device__ float g_s[BN * HDIM];
__device__ float g_t[BN * HDIM];
__device__ float g_hatt[BN * HDIM];
__device__ int   g_nbr[BN * MAXNB];
__device__ float g_nbrw[BN * MAXNB];
__device__ int   g_cnt[BN];
__device__ float g_sconst[HDIM];          // gc_b @ Ws^T + Ws_b
__device__ float g_tconst[HDIM];          // gc_b @ Wt^T + Wt_b
// transposed weights, PADDED by 8 k-rows for unguarded pipeline prefetch
__device__ float g_Wih_t[(IDIM + 8) * G4H];
__device__ float g_Whh_t[(HDIM + 8) * G4H];
__device__ float g_Wst_t[(HDIM + 8) * 2 * HDIM];   // col<128 Ws, col>=128 Wt
__device__ float g_comb_t[(2 * HDIM + 8) * HDIM];
__device__ float g_gcw[(HDIM + 8) * HDIM];         // padded copy of gc_w

__device__ __forceinline__ float sigm_fast(float x) {
    return __fdividef(1.0f, 1.0f + __expf(-x));
}
__device__ __forceinline__ float tanh_fast(float x) {
    float cx = fminf(fmaxf(x, -15.0f), 15.0f);
    float e = __expf(2.0f * cx);
    return __fdividef(e - 1.0f, e + 1.0f);
}

// ============================================================================
// K0: prep = weight transposes/copies + adjacency scan + s/t bias-constants.
// ============================================================================
#define TW_TOTAL (IDIM*G4H + HDIM*G4H + HDIM*2*HDIM + 2*HDIM*HDIM + HDIM*HDIM)
#define NTB ((TW_TOTAL + 255) / 256)
#define SCANB ((BN + 7) / 8)
__global__ void __launch_bounds__(256)
prep_kernel(const float* __restrict__ W_ih, const float* __restrict__ W_hh,
            const float* __restrict__ Ws_w, const float* __restrict__ Wt_w,
            const float* __restrict__ comb_w, const float* __restrict__ adj,
            const float* __restrict__ gc_w, const float* __restrict__ gc_b,
            const float* __restrict__ Ws_b, const float* __restrict__ Wt_b)
{
    if (blockIdx.x < NTB) {
        int idx = blockIdx.x * 256 + threadIdx.x;
        if (idx < IDIM * G4H) {                       // Wih_t [64][512]
            int k = idx >> 9, g = idx & 511;
            g_Wih_t[idx] = __ldg(W_ih + g * IDIM + k);
            return;
        }
        idx -= IDIM * G4H;
        if (idx < HDIM * G4H) {                       // Whh_t [128][512]
            int k = idx >> 9, g = idx & 511;
            g_Whh_t[idx] = __ldg(W_hh + g * HDIM + k);
            return;
        }
        idx -= HDIM * G4H;
        if (idx < HDIM * 2 * HDIM) {                  // Wst_t [128][256]
            int k = idx >> 8, o = idx & 255;
            g_Wst_t[idx] = (o < HDIM) ? __ldg(Ws_w + o * HDIM + k)
                                      : __ldg(Wt_w + (o - HDIM) * HDIM + k);
            return;
        }
        idx -= HDIM * 2 * HDIM;
        if (idx < 2 * HDIM * HDIM) {                  // comb_t [256][128]
            int k = idx >> 7, o = idx & 127;
            g_comb_t[idx] = __ldg(comb_w + o * 2 * HDIM + k);
            return;
        }
        idx -= 2 * HDIM * HDIM;
        if (idx < HDIM * HDIM) {                      // gcw copy (same layout)
            g_gcw[idx] = __ldg(gc_w + idx);
        }
        return;
    }

    if (blockIdx.x < NTB + SCANB) {
        // ---- adjacency scan: 8 warps, one row per warp, ballot compaction ----
        const int lane = threadIdx.x & 31;
        const int wrp  = threadIdx.x >> 5;
        const int row  = (blockIdx.x - NTB) * 8 + wrp;
        if (row >= BN) return;
        const int b = row / NNODES;
        const int i = row % NNODES;
        const float* arow = adj + (size_t)b * NNODES * NNODES + (size_t)i * NNODES;

        int cnt = 0;
        const unsigned lt = (1u << lane) - 1u;
        for (int j0 = 0; j0 < NNODES; j0 += 32) {
            int j = j0 + lane;
            float a = (j < NNODES) ? __ldg(arow + j) : 0.0f;
            unsigned m = __ballot_sync(0xffffffffu, a != 0.0f);
            int pos = cnt + __popc(m & lt);
            if (a != 0.0f && pos < MAXNB) {
                g_nbr[row * MAXNB + pos]  = j;
                g_nbrw[row * MAXNB + pos] = a;
            }
            cnt += __popc(m);
        }
        if (lane == 0) g_cnt[row] = min(cnt, MAXNB);
        return;
    }

    // ---- bias constants: sconst = gc_b @ Ws^T + Ws_b; tconst likewise ----
    __shared__ float gb[HDIM];
    int tid = threadIdx.x;
    if (tid < HDIM) gb[tid] = __ldg(gc_b + tid);
    __syncthreads();
    int o = tid & 127;
    const float* W = (tid < HDIM) ? (Ws_w + o * HDIM) : (Wt_w + o * HDIM);
    float acc = (tid < HDIM) ? __ldg(Ws_b + o) : __ldg(Wt_b + o);
#pragma unroll 8
    for (int k = 0; k < HDIM; k++)
        acc += gb[k] * __ldg(W + k);
    if (tid < HDIM) g_sconst[o] = acc;
    else            g_tconst[o] = acc;
}

// ============================================================================
// Software-pipelined column-GEMM core: acc[m] += sum_k sA[m][k] * Wcol[k].
// Wcol = W + column, row stride STRIDE; rows [0, 128) real, [128,136) padding.
// 2-stage register prefetch of 8 weights; L2 latency hidden behind FFMA.
// ============================================================================
#define PIPE_GEMM_128(WBASE, STRIDE, SA, MM, ACC)                              \
    do {                                                                       \
        float wA[8], wB[8];                                                    \
        _Pragma("unroll")                                                      \
        for (int j = 0; j < 8; j++) wA[j] = (WBASE)[j * (STRIDE)];             \
        _Pragma("unroll")                                                      \
        for (int k0 = 0; k0 < 128; k0 += 16) {                                 \
            _Pragma("unroll")                                                  \
            for (int j = 0; j < 8; j++)                                        \
                wB[j] = (WBASE)[(k0 + 8 + j) * (STRIDE)];                      \
            _Pragma("unroll")                                                  \
            for (int j4 = 0; j4 < 2; j4++)                                     \
                _Pragma("unroll")                                              \
                for (int m = 0; m < (MM); m++) {                               \
                    float4 a = *((const float4*)&(SA)[m][k0 + j4 * 4]);        \
                    (ACC)[m] += a.x * wA[j4*4+0] + a.y * wA[j4*4+1]            \
                              + a.z * wA[j4*4+2] + a.w * wA[j4*4+3];           \
                }                                                              \
            _Pragma("unroll")                                                  \
            for (int j = 0; j < 8; j++)                                        \
                wA[j] = (WBASE)[(k0 + 16 + j) * (STRIDE)];                     \
            _Pragma("unroll")                                                  \
            for (int j4 = 0; j4 < 2; j4++)                                     \
                _Pragma("unroll")                                              \
                for (int m = 0; m < (MM); m++) {                               \
                    float4 a = *((const float4*)&(SA)[m][k0 + 8 + j4 * 4]);    \
                    (ACC)[m] += a.x * wB[j4*4+0] + a.y * wB[j4*4+1]            \
                              + a.z * wB[j4*4+2] + a.w * wB[j4*4+3];           \
                }                                                              \
        }                                                                      \
    } while (0)

#define PIPE_GEMM_64(WBASE, STRIDE, SA, MM, ACC)                               \
    do {                                                                       \
        float wA[8], wB[8];                                                    \
        _Pragma("unroll")                                                      \
        for (int j = 0; j < 8; j++) wA[j] = (WBASE)[j * (STRIDE)];             \
        _Pragma("unroll")                                                      \
        for (int k0 = 0; k0 < 64; k0 += 16) {                                  \
            _Pragma("unroll")                                                  \
            for (int j = 0; j < 8; j++)                                        \
                wB[j] = (WBASE)[(k0 + 8 + j) * (STRIDE)];                      \
            _Pragma("unroll")                                                  \
            for (int j4 = 0; j4 < 2; j4++)                                     \
                _Pragma("unroll")                                              \
                for (int m = 0; m < (MM); m++) {                               \
                    float4 a = *((const float4*)&(SA)[m][k0 + j4 * 4]);        \
                    (ACC)[m] += a.x * wA[j4*4+0] + a.y * wA[j4*4+1]            \
                              + a.z * wA[j4*4+2] + a.w * wA[j4*4+3];           \
                }                                                              \
            _Pragma("unroll")                                                  \
            for (int j = 0; j < 8; j++)                                        \
                wA[j] = (WBASE)[(k0 + 16 + j) * (STRIDE)];                     \
            _Pragma("unroll")                                                  \
            for (int j4 = 0; j4 < 2; j4++)                                     \
                _Pragma("unroll")                                              \
                for (int m = 0; m < (MM); m++) {                               \
                    float4 a = *((const float4*)&(SA)[m][k0 + 8 + j4 * 4]);    \
                    (ACC)[m] += a.x * wB[j4*4+0] + a.y * wB[j4*4+1]            \
                              + a.z * wB[j4*4+2] + a.w * wB[j4*4+3];           \
                }                                                              \
        }                                                                      \
    } while (0)

// ============================================================================
// K1: LSTM gates GEMM.  Grid (325, 4), 128 thr, m=4, pipelined.
// ============================================================================
#define LM 4
__global__ void __launch_bounds__(128)
lstm_gemm_kernel(const float* __restrict__ x, const float* __restrict__ h,
                 const float* __restrict__ b_ih, const float* __restrict__ b_hh)
{
    __shared__ __align__(16) float sx[LM][IDIM];
    __shared__ __align__(16) float sh[LM][HDIM];

    const int node0 = blockIdx.x * LM;
    const int o = threadIdx.x;
    const int g = blockIdx.y * HDIM + o;

    for (int idx = o; idx < LM * IDIM; idx += 128) {
        int m = idx >> 6, k = idx & 63;
        sx[m][k] = x[(node0 + m) * IDIM + k];
    }
    for (int idx = o; idx < LM * HDIM; idx += 128) {
        int m = idx >> 7, k = idx & 127;
        sh[m][k] = h[(node0 + m) * HDIM + k];
    }
    __syncthreads();

    float acc[LM];
    const float bb = __ldg(b_ih + g) + __ldg(b_hh + g);
#pragma unroll
    for (int m = 0; m < LM; m++) acc[m] = bb;

    PIPE_GEMM_64(g_Wih_t + g, G4H, sx, LM, acc);
    PIPE_GEMM_128(g_Whh_t + g, G4H, sh, LM, acc);

#pragma unroll
    for (int m = 0; m < LM; m++)
        g_gates[(node0 + m) * G4H + g] = acc[m];
}

// ============================================================================
// K2: LSTM activations + support GEMM (m=2, pipelined).  650 blocks.
// ============================================================================
__global__ void __launch_bounds__(128)
act_support_kernel(const float* __restrict__ c, float* __restrict__ c_out)
{
    __shared__ __align__(16) float shh[2][HDIM];
    const int node0 = blockIdx.x * 2;
    const int u = threadIdx.x;

#pragma unroll
    for (int m = 0; m < 2; m++) {
        int node = node0 + m;
        const float* gb = g_gates + node * G4H;
        float ig = sigm_fast(gb[u]);
        float fg = sigm_fast(gb[HDIM + u]);
        float gg = tanh_fast(gb[2 * HDIM + u]);
        float og = sigm_fast(gb[3 * HDIM + u]);
        float cc = fg * c[node * HDIM + u] + ig * gg;
        float hh = og * tanh_fast(cc);
        c_out[node * HDIM + u] = cc;
        g_h_lstm[node * HDIM + u] = hh;
        shh[m][u] = hh;
    }
    __syncthreads();

    float acc[2] = {0.f, 0.f};
    PIPE_GEMM_128(g_gcw + u, HDIM, shh, 2, acc);
    g_support[node0 * HDIM + u] = acc[0];
    g_support[(node0 + 1) * HDIM + u] = acc[1];
}

// ============================================================================
// K3: P|Q GEMM, m=4, pipelined.  Grid (325, 2).
// ============================================================================
__global__ void __launch_bounds__(128)
pq_kernel()
{
    __shared__ __align__(16) float sA[LM][HDIM];
    const int node0 = blockIdx.x * LM;
    const int o = threadIdx.x;
    const int oc = blockIdx.y * HDIM + o;   // column in fused Wst [128][256]

    for (int idx = o; idx < LM * HDIM; idx += 128) {
        int m = idx >> 7, k = idx & 127;
        sA[m][k] = g_support[(node0 + m) * HDIM + k];
    }
    __syncthreads();

    float acc[LM] = {0.f, 0.f, 0.f, 0.f};
    PIPE_GEMM_128(g_Wst_t + oc, 2 * HDIM, sA, LM, acc);

    float* C = blockIdx.y ? g_Q : g_P;
#pragma unroll
    for (int m = 0; m < LM; m++)
        C[(node0 + m) * HDIM + o] = acc[m];
}

// ============================================================================
// K4: triple sparse gather (no weight reads), 4x unrolled.  1300 blocks.
// ============================================================================
__global__ void __launch_bounds__(128)
gather_kernel(const float* __restrict__ gc_b)
{
    const int row = blockIdx.x;
    const int b = row / NNODES;
    const int tid = threadIdx.x;

    __shared__ int   lst[MAXNB];
    __shared__ float wv[MAXNB];

    const int cn = g_cnt[row];
    for (int t = tid; t < cn; t += 128) {
        lst[t] = g_nbr[row * MAXNB + t];
        wv[t]  = g_nbrw[row * MAXNB + t];
    }
    __syncthreads();

    const int u = tid;
    float ah = __ldg(gc_b + u);
    float as = g_sconst[u];
    float at = g_tconst[u];
    const size_t base = (size_t)b * NNODES * HDIM + u;

    int t = 0;
    for (; t + 4 <= cn; t += 4) {
        size_t o0 = base + (size_t)lst[t]     * HDIM;
        size_t o1 = base + (size_t)lst[t + 1] * HDIM;
        size_t o2 = base + (size_t)lst[t + 2] * HDIM;
        size_t o3 = base + (size_t)lst[t + 3] * HDIM;
        float w0 = wv[t], w1 = wv[t + 1], w2 = wv[t + 2], w3 = wv[t + 3];
        float h0 = g_support[o0], h1 = g_support[o1], h2 = g_support[o2], h3 = g_support[o3];
        float p0 = g_P[o0], p1 = g_P[o1], p2 = g_P[o2], p3 = g_P[o3];
        float q0 = g_Q[o0], q1 = g_Q[o1], q2 = g_Q[o2], q3 = g_Q[o3];
        ah += w0 * h0 + w1 * h1 + w2 * h2 + w3 * h3;
        as += w0 * p0 + w1 * p1 + w2 * p2 + w3 * p3;
        at += w0 * q0 + w1 * q1 + w2 * q2 + w3 * q3;
    }
    for (; t < cn; t++) {
        size_t off = base + (size_t)lst[t] * HDIM;
        float w = wv[t];
        ah += w * g_support[off];
        as += w * g_P[off];
        at += w * g_Q[off];
    }
    g_hgraph[row * HDIM + u] = ah;
    g_s[row * HDIM + u] = as;
    g_t[row * HDIM + u] = at;
}

// ============================================================================
// K5: attention + softmax + context + LayerNorm.  1300 blocks, 128 threads.
// ============================================================================
__global__ void __launch_bounds__(128)
attn_kernel(const float* __restrict__ v, const float* __restrict__ ln_g,
            const float* __restrict__ ln_b)
{
    const int row = blockIdx.x;
    const int b = row / NNODES;
    const int tid = threadIdx.x;
    const int lane = tid & 31;
    const int wrp = tid >> 5;

    __shared__ float s_sh[HDIM];
    __shared__ float v_sh[HDIM];
    __shared__ float sc[MAXNB];
    __shared__ int   lst[MAXNB];
    __shared__ float red1[4], red2[4];

    s_sh[tid] = g_s[row * HDIM + tid];
    v_sh[tid] = __ldg(v + tid);
    const int cn = g_cnt[row];
    for (int t = tid; t < cn; t += 128) lst[t] = g_nbr[row * MAXNB + t];
    __syncthreads();

    // scores: 4 warps t-strided; lanes over features
    const float* tb = g_t + (size_t)b * NNODES * HDIM;
    for (int t = wrp; t < cn; t += 4) {
        const float* tj = tb + (size_t)lst[t] * HDIM;
        float x0 = __ldg(tj + lane);
        float x1 = __ldg(tj + lane + 32);
        float x2 = __ldg(tj + lane + 64);
        float x3 = __ldg(tj + lane + 96);
        float p = tanh_fast(s_sh[lane] + x0) * v_sh[lane]
                + tanh_fast(s_sh[lane + 32] + x1) * v_sh[lane + 32]
                + tanh_fast(s_sh[lane + 64] + x2) * v_sh[lane + 64]
                + tanh_fast(s_sh[lane + 96] + x3) * v_sh[lane + 96];
#pragma unroll
        for (int off = 16; off > 0; off >>= 1)
            p += __shfl_xor_sync(0xffffffffu, p, off);
        if (lane == 0) sc[t] = p;
    }
    __syncthreads();

    // softmax (warp 0)
    if (wrp == 0) {
        float mx = -1e30f;
        for (int t = lane; t < cn; t += 32) mx = fmaxf(mx, sc[t]);
#pragma unroll
        for (int off = 16; off > 0; off >>= 1)
            mx = fmaxf(mx, __shfl_xor_sync(0xffffffffu, mx, off));
        float sm = 0.0f;
        for (int t = lane; t < cn; t += 32) {
            float e = __expf(sc[t] - mx);
            sc[t] = e;
            sm += e;
        }
#pragma unroll
        for (int off = 16; off > 0; off >>= 1)
            sm += __shfl_xor_sync(0xffffffffu, sm, off);
        float inv = __fdividef(1.0f, sm);
        for (int t = lane; t < cn; t += 32) sc[t] *= inv;
    }
    __syncthreads();

    // context: thread = feature u, 4x unrolled neighbor loop
    const int u = tid;
    float acc = 0.0f;
    const float* hgb = g_hgraph + (size_t)b * NNODES * HDIM;
    int t = 0;
    for (; t + 4 <= cn; t += 4) {
        float h0 = __ldg(hgb + (size_t)lst[t]     * HDIM + u);
        float h1 = __ldg(hgb + (size_t)lst[t + 1] * HDIM + u);
        float h2 = __ldg(hgb + (size_t)lst[t + 2] * HDIM + u);
        float h3 = __ldg(hgb + (size_t)lst[t + 3] * HDIM + u);
        acc += sc[t] * h0 + sc[t + 1] * h1 + sc[t + 2] * h2 + sc[t + 3] * h3;
    }
    for (; t < cn; t++)
        acc += sc[t] * __ldg(hgb + (size_t)lst[t] * HDIM + u);

    // LayerNorm
    float s1 = acc, s2 = acc * acc;
#pragma unroll
    for (int off = 16; off > 0; off >>= 1) {
        s1 += __shfl_xor_sync(0xffffffffu, s1, off);
        s2 += __shfl_xor_sync(0xffffffffu, s2, off);
    }
    if (lane == 0) { red1[wrp] = s1; red2[wrp] = s2; }
    __syncthreads();
    float tot1 = red1[0] + red1[1] + red1[2] + red1[3];
    float tot2 = red2[0] + red2[1] + red2[2] + red2[3];
    float mu = tot1 * (1.0f / HDIM);
    float var = tot2 * (1.0f / HDIM) - mu * mu;
    g_hatt[row * HDIM + u] =
        __ldg(ln_g + u) * (acc - mu) * rsqrtf(var + LN_EPS) + __ldg(ln_b + u);
}

// ============================================================================
// K6: combine GEMM, m=2, pipelined:  out = [hl|ha] @ comb^T + comb_b.
// 650 blocks, 128 threads, K=256 (two pipelined 128-row passes).
// ============================================================================
__global__ void __launch_bounds__(128)
comb_kernel(const float* __restrict__ comb_b, float* __restrict__ out)
{
    __shared__ __align__(16) float shl[2][HDIM];
    __shared__ __align__(16) float sha[2][HDIM];
    const int node0 = blockIdx.x * 2;
    const int o = threadIdx.x;

    for (int idx = o; idx < 2 * HDIM; idx += 128) {
        int m = idx >> 7, k = idx & 127;
        shl[m][k] = g_h_lstm[(node0 + m) * HDIM + k];
        sha[m][k] = g_hatt[(node0 + m) * HDIM + k];
    }
    __syncthreads();

    const float cb = __ldg(comb_b + o);
    float acc[2] = {cb, cb};
    PIPE_GEMM_128(g_comb_t + o, HDIM, shl, 2, acc);
    PIPE_GEMM_128(g_comb_t + HDIM * HDIM + o, HDIM, sha, 2, acc);
    out[node0 * HDIM + o] = acc[0];
    out[(node0 + 1) * HDIM + o] = acc[1];
}

// ============================================================================
extern "C" void kernel_launch(void* const* d_in, const int* in_sizes, int n_in,
                              void* d_out, int out_size)
{
    const float* x      = (const float*)d_in[0];
    const float* adj    = (const float*)d_in[1];
    const float* h      = (const float*)d_in[2];
    const float* c      = (const float*)d_in[3];
    const float* W_ih   = (const float*)d_in[4];
    const float* W_hh   = (const float*)d_in[5];
    const float* b_ih   = (const float*)d_in[6];
    const float* b_hh   = (const float*)d_in[7];
    const float* gc_w   = (const float*)d_in[8];
    const float* gc_b   = (const float*)d_in[9];
    const float* Ws_w   = (const float*)d_in[10];
    const float* Ws_b   = (const float*)d_in[11];
    const float* Wt_w   = (const float*)d_in[12];
    const float* Wt_b   = (const float*)d_in[13];
    const float* v      = (const float*)d_in[14];
    const float* ln_g   = (const float*)d_in[15];
    const float* ln_b   = (const float*)d_in[16];
    const float* comb_w = (const float*)d_in[17];
    const float* comb_b = (const float*)d_in[18];

    float* out = (float*)d_out;              // h_new, then c_lstm
    float* c_out = out + (size_t)BN * HDIM;

    prep_kernel<<<NTB + SCANB + 1, 256>>>(W_ih, W_hh, Ws_w, Wt_w, comb_w, adj,
                                          gc_w, gc_b, Ws_b, Wt_b);
    dim3 lstm_grid(BN / LM, 4);                        // 325 x 4 = 1300
    lstm_gemm_kernel<<<lstm_grid, 128>>>(x, h, b_ih, b_hh);
    act_support_kernel<<<BN / 2, 128>>>(c, c_out);     // 650
    dim3 pq_grid(BN / LM, 2);                          // 325 x 2 = 650
    pq_kernel<<<pq_grid, 128>>>();
    gather_kernel<<<BN, 128>>>(gc_b);                  // 1300
    attn_kernel<<<BN, 128>>>(v, ln_g, ln_b);           // 1300
    comb_kernel<<<BN / 2, 128>>>(comb_b, out);         // 650
}